// round 1
// baseline (speedup 1.0000x reference)
#include <cuda_runtime.h>
#include <cstdint>

#define BB 2
#define TT 2048
#define DD 768
#define HH 12
#define DH 64
#define BT (BB*TT)

// ---------------- scratch (static device arrays; no allocation) ----------------
__device__ float g_qkv [(size_t)BT * 2304];
__device__ float g_attn[(size_t)BT * DD];
__device__ float g_proj[(size_t)BT * DD];
__device__ float g_n   [(size_t)BT * DD];
__device__ float g_h1  [(size_t)BT * 3072];
__device__ float g_m   [(size_t)BT * DD];

// ---------------- SGEMM: C[M,N] = A[M,K] @ W[K,N] + bias, optional GELU --------
// BM=128 BN=128 BK=16, 256 threads, 8x8 micro-tile per thread.
__global__ __launch_bounds__(256)
void sgemm_bias(const float* __restrict__ A, const float* __restrict__ W,
                const float* __restrict__ bias, float* __restrict__ C,
                int M, int N, int K, int do_gelu)
{
    __shared__ float As[16][128];
    __shared__ float Bs[16][128];

    const int tid = threadIdx.x;
    const int tx = tid & 15;          // 0..15  (cols)
    const int ty = tid >> 4;          // 0..15  (rows)
    const int row0 = blockIdx.y * 128;
    const int col0 = blockIdx.x * 128;

    float acc[8][8];
#pragma unroll
    for (int i = 0; i < 8; i++)
#pragma unroll
        for (int j = 0; j < 8; j++) acc[i][j] = 0.f;

    for (int k0 = 0; k0 < K; k0 += 16) {
        // A tile: 128 rows x 16 cols  -> 512 float4, 2 per thread (transposed store)
#pragma unroll
        for (int l = 0; l < 2; l++) {
            int idx = tid + l * 256;          // 0..511
            int r = idx >> 2;                 // 0..127
            int c = (idx & 3) * 4;            // 0,4,8,12
            float4 v = *reinterpret_cast<const float4*>(&A[(size_t)(row0 + r) * K + k0 + c]);
            As[c + 0][r] = v.x; As[c + 1][r] = v.y;
            As[c + 2][r] = v.z; As[c + 3][r] = v.w;
        }
        // B tile: 16 rows x 128 cols -> 512 float4, 2 per thread
#pragma unroll
        for (int l = 0; l < 2; l++) {
            int idx = tid + l * 256;
            int r = idx >> 5;                 // 0..15
            int c = (idx & 31) * 4;           // 0..124
            float4 v = *reinterpret_cast<const float4*>(&W[(size_t)(k0 + r) * N + col0 + c]);
            *reinterpret_cast<float4*>(&Bs[r][c]) = v;
        }
        __syncthreads();

#pragma unroll
        for (int kk = 0; kk < 16; kk++) {
            float af[8], bf[8];
            float4 a0 = *reinterpret_cast<const float4*>(&As[kk][ty * 8]);
            float4 a1 = *reinterpret_cast<const float4*>(&As[kk][ty * 8 + 4]);
            float4 b0 = *reinterpret_cast<const float4*>(&Bs[kk][tx * 8]);
            float4 b1 = *reinterpret_cast<const float4*>(&Bs[kk][tx * 8 + 4]);
            af[0]=a0.x; af[1]=a0.y; af[2]=a0.z; af[3]=a0.w;
            af[4]=a1.x; af[5]=a1.y; af[6]=a1.z; af[7]=a1.w;
            bf[0]=b0.x; bf[1]=b0.y; bf[2]=b0.z; bf[3]=b0.w;
            bf[4]=b1.x; bf[5]=b1.y; bf[6]=b1.z; bf[7]=b1.w;
#pragma unroll
            for (int i = 0; i < 8; i++)
#pragma unroll
                for (int j = 0; j < 8; j++)
                    acc[i][j] += af[i] * bf[j];
        }
        __syncthreads();
    }

#pragma unroll
    for (int i = 0; i < 8; i++) {
        int row = row0 + ty * 8 + i;
#pragma unroll
        for (int j = 0; j < 8; j++) {
            int col = col0 + tx * 8 + j;
            float v = acc[i][j] + bias[col];
            if (do_gelu) {
                float u = v;
                v = 0.5f * u * (1.0f + tanhf(0.7978845608028654f * (u + 0.044715f * u * u * u)));
            }
            C[(size_t)row * N + col] = v;
        }
    }
}

// ---------------- Flash attention (no scale), ragged key/query mask ------------
// grid: (T/64, H, B), 256 threads. 64 queries x 64 dims per CTA.
__global__ __launch_bounds__(256)
void attn_kernel(const float* __restrict__ qkv, const int* __restrict__ lengths,
                 float* __restrict__ aout)
{
    extern __shared__ float sm[];
    float* Qt = sm;                   // [d][q]  stride 68
    float* Kt = Qt + 64 * 68;         // [d][k]  stride 68
    float* Vs = Kt + 64 * 68;         // [k][d]  stride 68
    float* Pt = Vs + 64 * 68;         // [k][q]  stride 68
    __shared__ float mrow[64], lrow[64], srow[64];

    const int qtile = blockIdx.x;
    const int h = blockIdx.y;
    const int b = blockIdx.z;
    const int len = lengths[b];
    const int tid = threadIdx.x;
    const int tx = tid & 15;
    const int ty = tid >> 4;
    const int t0 = qtile * 64;

    const size_t baseQ = (size_t)b * TT * 2304 + (size_t)h * DH;
    const size_t baseK = baseQ + DD;
    const size_t baseV = baseQ + 2 * DD;

    // load Q tile transposed (d-major)
    for (int i = tid; i < 64 * 64; i += 256) {
        int q = i >> 6, d = i & 63;
        Qt[d * 68 + q] = qkv[baseQ + (size_t)(t0 + q) * 2304 + d];
    }
    if (tid < 64) { mrow[tid] = -1e30f; lrow[tid] = 0.f; }

    float O[4][4];
#pragma unroll
    for (int i = 0; i < 4; i++)
#pragma unroll
        for (int j = 0; j < 4; j++) O[i][j] = 0.f;

    const int ntiles = (len + 63) >> 6;
    for (int kt = 0; kt < ntiles; kt++) {
        const int k0 = kt * 64;
        __syncthreads();   // protect Pt/Kt/Vs from previous iteration & Q/m/l init
        for (int i = tid; i < 64 * 64; i += 256) {
            int k = i >> 6, d = i & 63;
            Kt[d * 68 + k] = qkv[baseK + (size_t)(k0 + k) * 2304 + d];
            Vs[k * 68 + d] = qkv[baseV + (size_t)(k0 + k) * 2304 + d];
        }
        __syncthreads();

        // S = Q @ K^T  (4x4 per thread: q = ty*4+i, k = tx*4+j)
        float sacc[4][4];
#pragma unroll
        for (int i = 0; i < 4; i++)
#pragma unroll
            for (int j = 0; j < 4; j++) sacc[i][j] = 0.f;

        for (int d = 0; d < 64; d++) {
            float4 q4 = *reinterpret_cast<const float4*>(&Qt[d * 68 + ty * 4]);
            float4 k4 = *reinterpret_cast<const float4*>(&Kt[d * 68 + tx * 4]);
            float qa[4] = {q4.x, q4.y, q4.z, q4.w};
            float kb[4] = {k4.x, k4.y, k4.z, k4.w};
#pragma unroll
            for (int i = 0; i < 4; i++)
#pragma unroll
                for (int j = 0; j < 4; j++)
                    sacc[i][j] += qa[i] * kb[j];
        }

        // write (masked) scores to Pt[k][q]
#pragma unroll
        for (int j = 0; j < 4; j++) {
            int kg = k0 + tx * 4 + j;
            bool ok = (kg < len);
#pragma unroll
            for (int i = 0; i < 4; i++)
                Pt[(tx * 4 + j) * 68 + ty * 4 + i] = ok ? sacc[i][j] : -1e30f;
        }
        __syncthreads();

        // online softmax per row (64 threads, one row each)
        if (tid < 64) {
            int q = tid;
            float m_old = mrow[q];
            float mx = m_old;
            for (int k = 0; k < 64; k++) mx = fmaxf(mx, Pt[k * 68 + q]);
            float scale = __expf(m_old - mx);
            float ssum = 0.f;
            for (int k = 0; k < 64; k++) {
                float p = __expf(Pt[k * 68 + q] - mx);
                Pt[k * 68 + q] = p;
                ssum += p;
            }
            lrow[q] = lrow[q] * scale + ssum;
            mrow[q] = mx;
            srow[q] = scale;
        }
        __syncthreads();

        // rescale O, accumulate P @ V
        float sc[4];
#pragma unroll
        for (int i = 0; i < 4; i++) sc[i] = srow[ty * 4 + i];
#pragma unroll
        for (int i = 0; i < 4; i++)
#pragma unroll
            for (int j = 0; j < 4; j++) O[i][j] *= sc[i];

        for (int k = 0; k < 64; k++) {
            float4 p4 = *reinterpret_cast<const float4*>(&Pt[k * 68 + ty * 4]);
            float4 v4 = *reinterpret_cast<const float4*>(&Vs[k * 68 + tx * 4]);
            float pa[4] = {p4.x, p4.y, p4.z, p4.w};
            float vb[4] = {v4.x, v4.y, v4.z, v4.w};
#pragma unroll
            for (int i = 0; i < 4; i++)
#pragma unroll
                for (int j = 0; j < 4; j++)
                    O[i][j] += pa[i] * vb[j];
        }
    }

    // write out: divide by l, zero invalid query rows
#pragma unroll
    for (int i = 0; i < 4; i++) {
        int t = t0 + ty * 4 + i;
        float inv = (t < len) ? (1.f / lrow[ty * 4 + i]) : 0.f;
#pragma unroll
        for (int j = 0; j < 4; j++)
            aout[((size_t)b * TT + t) * DD + h * DH + tx * 4 + j] = O[i][j] * inv;
    }
}

// ---------------- residual + LayerNorm + mask ----------------------------------
__global__ __launch_bounds__(256)
void ln_kernel(const float* __restrict__ a, const float* __restrict__ r,
               const float* __restrict__ g, const float* __restrict__ beta,
               const int* __restrict__ lengths, float* __restrict__ out)
{
    const int row = blockIdx.x;
    const int t = row & (TT - 1);
    const int bi = row >> 11;
    const float maskv = (t < lengths[bi]) ? 1.f : 0.f;
    const float* pa = a + (size_t)row * DD;
    const float* pr = r + (size_t)row * DD;

    float s = 0.f, s2 = 0.f;
    for (int i = threadIdx.x; i < DD; i += 256) {
        float v = pa[i] + pr[i];
        s += v; s2 += v * v;
    }
#pragma unroll
    for (int o = 16; o; o >>= 1) {
        s  += __shfl_down_sync(0xffffffffu, s,  o);
        s2 += __shfl_down_sync(0xffffffffu, s2, o);
    }
    __shared__ float ws[8], ws2[8];
    int w = threadIdx.x >> 5, lane = threadIdx.x & 31;
    if (lane == 0) { ws[w] = s; ws2[w] = s2; }
    __syncthreads();
    if (threadIdx.x == 0) {
        float S = 0.f, S2 = 0.f;
        for (int i = 0; i < 8; i++) { S += ws[i]; S2 += ws2[i]; }
        ws[0] = S; ws2[0] = S2;
    }
    __syncthreads();
    const float mu = ws[0] * (1.f / DD);
    const float var = ws2[0] * (1.f / DD) - mu * mu;
    const float rstd = rsqrtf(var + 1e-5f);
    for (int i = threadIdx.x; i < DD; i += 256) {
        float v = pa[i] + pr[i];
        out[(size_t)row * DD + i] = ((v - mu) * rstd * g[i] + beta[i]) * maskv;
    }
}

// ---------------- launcher ------------------------------------------------------
extern "C" void kernel_launch(void* const* d_in, const int* in_sizes, int n_in,
                              void* d_out, int out_size)
{
    const float* x      = (const float*)d_in[0];
    const int*   lens   = (const int*)  d_in[1];
    const float* w_qkv  = (const float*)d_in[2];
    const float* b_qkv  = (const float*)d_in[3];
    const float* w_proj = (const float*)d_in[4];
    const float* b_proj = (const float*)d_in[5];
    const float* ln1_g  = (const float*)d_in[6];
    const float* ln1_b  = (const float*)d_in[7];
    const float* w_fc   = (const float*)d_in[8];
    const float* b_fc   = (const float*)d_in[9];
    const float* w_out  = (const float*)d_in[10];
    const float* b_out  = (const float*)d_in[11];
    const float* ln2_g  = (const float*)d_in[12];
    const float* ln2_b  = (const float*)d_in[13];
    float* out = (float*)d_out;

    float *p_qkv, *p_attn, *p_proj, *p_n, *p_h1, *p_m;
    cudaGetSymbolAddress((void**)&p_qkv,  g_qkv);
    cudaGetSymbolAddress((void**)&p_attn, g_attn);
    cudaGetSymbolAddress((void**)&p_proj, g_proj);
    cudaGetSymbolAddress((void**)&p_n,    g_n);
    cudaGetSymbolAddress((void**)&p_h1,   g_h1);
    cudaGetSymbolAddress((void**)&p_m,    g_m);

    const int ATTN_SMEM = 4 * 64 * 68 * (int)sizeof(float);   // 69632 B
    cudaFuncSetAttribute(attn_kernel, cudaFuncAttributeMaxDynamicSharedMemorySize, ATTN_SMEM);

    // 1) qkv = x @ w_qkv + b_qkv                [4096, 2304]
    sgemm_bias<<<dim3(2304 / 128, BT / 128), 256>>>(x, w_qkv, b_qkv, p_qkv, BT, 2304, DD, 0);

    // 2) attention                              [4096, 768]
    attn_kernel<<<dim3(TT / 64, HH, BB), 256, ATTN_SMEM>>>(p_qkv, lens, p_attn);

    // 3) proj = attn @ w_proj + b_proj          [4096, 768]
    sgemm_bias<<<dim3(DD / 128, BT / 128), 256>>>(p_attn, w_proj, b_proj, p_proj, BT, DD, DD, 0);

    // 4) n = LN(x + proj) * mask                [4096, 768]
    ln_kernel<<<BT, 256>>>(x, p_proj, ln1_g, ln1_b, lens, p_n);

    // 5) h1 = gelu(n @ w_fc + b_fc)             [4096, 3072]
    sgemm_bias<<<dim3(3072 / 128, BT / 128), 256>>>(p_n, w_fc, b_fc, p_h1, BT, 3072, DD, 1);

    // 6) m = h1 @ w_out + b_out                 [4096, 768]
    sgemm_bias<<<dim3(DD / 128, BT / 128), 256>>>(p_h1, w_out, b_out, p_m, BT, DD, 3072, 0);

    // 7) out = LN(n + m) * mask                 [4096, 768]
    ln_kernel<<<BT, 256>>>(p_n, p_m, ln2_g, ln2_b, lens, out);
}